// round 6
// baseline (speedup 1.0000x reference)
#include <cuda_runtime.h>

#define NUM_C 8192
#define NUM_B 256
#define RPB   2                       // rows per block
#define NBLK  (NUM_B / RPB)           // 128 -> single wave on 148 SMs
#define NT    512
#define NWARP (NT / 32)
#define EPSF  1e-6f

// cross-block accumulators (allocation-free rule: __device__ globals; reset
// in-kernel after the grid completes so every graph replay starts clean)
__device__ float        g_sum = 0.0f;
__device__ unsigned int g_cnt = 0u;

__device__ __forceinline__ int hot_lane(int4 t, int j) {
    // t is a one-hot float row chunk reinterpreted as ints (1.0f != 0 bits)
    return t.x ? j : (t.y ? j + 1 : (t.z ? j + 2 : j + 3));
}

__global__ __launch_bounds__(NT)
void seesaw_v6_kernel(const float* __restrict__ logits,
                      const float* __restrict__ targets,
                      const float* __restrict__ s,
                      float* __restrict__ out)
{
    __shared__ float sh_warp0[NWARP];
    __shared__ float sh_warp1[NWARP];
    __shared__ int   sh_label[RPB];

    const int tid  = threadIdx.x;
    const int lane = tid & 31;
    const int wid  = tid >> 5;

    const int b0 = blockIdx.x * RPB;
    const int b1 = b0 + 1;
    const size_t off0 = (size_t)b0 * NUM_C;
    const size_t off1 = (size_t)b1 * NUM_C;

    // ---- front: issue ALL label-independent loads (16 in flight/thread) ----
    const int4*   tA = (const int4*)(targets + off0);
    const int4*   tB = (const int4*)(targets + off1);
    const float4* lA = (const float4*)(logits + off0);
    const float4* lB = (const float4*)(logits + off1);

    int4 ta0 = tA[tid + 0 * NT], ta1 = tA[tid + 1 * NT],
         ta2 = tA[tid + 2 * NT], ta3 = tA[tid + 3 * NT];
    int4 tb0 = tB[tid + 0 * NT], tb1 = tB[tid + 1 * NT],
         tb2 = tB[tid + 2 * NT], tb3 = tB[tid + 3 * NT];

    float4 la0 = lA[tid + 0 * NT], la1 = lA[tid + 1 * NT],
           la2 = lA[tid + 2 * NT], la3 = lA[tid + 3 * NT];
    float4 lb0 = lB[tid + 0 * NT], lb1 = lB[tid + 1 * NT],
           lb2 = lB[tid + 2 * NT], lb3 = lB[tid + 3 * NT];

    // ---- resolve both labels from landed targets regs ----
    {
        int l0 = -1, l1 = -1;
        if (ta0.x | ta0.y | ta0.z | ta0.w) l0 = hot_lane(ta0, (tid + 0 * NT) * 4);
        if (ta1.x | ta1.y | ta1.z | ta1.w) l0 = hot_lane(ta1, (tid + 1 * NT) * 4);
        if (ta2.x | ta2.y | ta2.z | ta2.w) l0 = hot_lane(ta2, (tid + 2 * NT) * 4);
        if (ta3.x | ta3.y | ta3.z | ta3.w) l0 = hot_lane(ta3, (tid + 3 * NT) * 4);
        if (tb0.x | tb0.y | tb0.z | tb0.w) l1 = hot_lane(tb0, (tid + 0 * NT) * 4);
        if (tb1.x | tb1.y | tb1.z | tb1.w) l1 = hot_lane(tb1, (tid + 1 * NT) * 4);
        if (tb2.x | tb2.y | tb2.z | tb2.w) l1 = hot_lane(tb2, (tid + 2 * NT) * 4);
        if (tb3.x | tb3.y | tb3.z | tb3.w) l1 = hot_lane(tb3, (tid + 3 * NT) * 4);
        if (l0 >= 0) sh_label[0] = l0;       // exactly one thread each
        if (l1 >= 0) sh_label[1] = l1;
    }
    __syncthreads();
    const int labA = sh_label[0];
    const int labB = sh_label[1];

    // ---- label-dependent phase: stream both s rows, fold with exp(logits).
    //      (s diag==1 folds the +expl term; max-shift dropped: it only
    //       rescales +eps by e^{-max}, ~1e-8 relative effect on sigma) ----
    const float4* sA = (const float4*)(s + (size_t)labA * NUM_C);
    const float4* sB = (const float4*)(s + (size_t)labB * NUM_C);

    float4 sa0 = sA[tid + 0 * NT], sa1 = sA[tid + 1 * NT],
           sa2 = sA[tid + 2 * NT], sa3 = sA[tid + 3 * NT];
    float4 sb0 = sB[tid + 0 * NT], sb1 = sB[tid + 1 * NT],
           sb2 = sB[tid + 2 * NT], sb3 = sB[tid + 3 * NT];

    float acc0 = 0.f, acc1 = 0.f;
    acc0 += sa0.x * __expf(la0.x) + sa0.y * __expf(la0.y)
          + sa0.z * __expf(la0.z) + sa0.w * __expf(la0.w);
    acc0 += sa1.x * __expf(la1.x) + sa1.y * __expf(la1.y)
          + sa1.z * __expf(la1.z) + sa1.w * __expf(la1.w);
    acc0 += sa2.x * __expf(la2.x) + sa2.y * __expf(la2.y)
          + sa2.z * __expf(la2.z) + sa2.w * __expf(la2.w);
    acc0 += sa3.x * __expf(la3.x) + sa3.y * __expf(la3.y)
          + sa3.z * __expf(la3.z) + sa3.w * __expf(la3.w);

    acc1 += sb0.x * __expf(lb0.x) + sb0.y * __expf(lb0.y)
          + sb0.z * __expf(lb0.z) + sb0.w * __expf(lb0.w);
    acc1 += sb1.x * __expf(lb1.x) + sb1.y * __expf(lb1.y)
          + sb1.z * __expf(lb1.z) + sb1.w * __expf(lb1.w);
    acc1 += sb2.x * __expf(lb2.x) + sb2.y * __expf(lb2.y)
          + sb2.z * __expf(lb2.z) + sb2.w * __expf(lb2.w);
    acc1 += sb3.x * __expf(lb3.x) + sb3.y * __expf(lb3.y)
          + sb3.z * __expf(lb3.z) + sb3.w * __expf(lb3.w);

    // ---- dual block reduce ----
    #pragma unroll
    for (int off = 16; off > 0; off >>= 1) {
        acc0 += __shfl_down_sync(0xffffffffu, acc0, off);
        acc1 += __shfl_down_sync(0xffffffffu, acc1, off);
    }
    if (lane == 0) { sh_warp0[wid] = acc0; sh_warp1[wid] = acc1; }
    __syncthreads();

    if (wid == 0) {
        float v0 = (lane < NWARP) ? sh_warp0[lane] : 0.f;
        float v1 = (lane < NWARP) ? sh_warp1[lane] : 0.f;
        #pragma unroll
        for (int off = 8; off > 0; off >>= 1) {
            v0 += __shfl_down_sync(0xffffffffu, v0, off);
            v1 += __shfl_down_sync(0xffffffffu, v1, off);
        }

        if (lane == 0) {
            float eA = __expf(__ldg(logits + off0 + labA));   // L2-hot
            float eB = __expf(__ldg(logits + off1 + labB));
            float loss0 = -logf(eA / (v0 + EPSF) + EPSF);
            float loss1 = -logf(eB / (v1 + EPSF) + EPSF);

            atomicAdd(&g_sum, loss0 + loss1);
            __threadfence();
            unsigned int tkt = atomicAdd(&g_cnt, 1u);
            if (tkt == NBLK - 1u) {
                float total = atomicExch(&g_sum, 0.0f);       // drain + reset
                g_cnt = 0u;
                out[0] = total * (1.0f / NUM_B);
            }
        }
    }
}

extern "C" void kernel_launch(void* const* d_in, const int* in_sizes, int n_in,
                              void* d_out, int out_size)
{
    const float* logits  = (const float*)d_in[0];
    const float* targets = (const float*)d_in[1];
    const float* s       = (const float*)d_in[2];
    float* out = (float*)d_out;

    seesaw_v6_kernel<<<NBLK, NT>>>(logits, targets, s, out);
}

// round 7
// speedup vs baseline: 1.0148x; 1.0148x over previous
#include <cuda_runtime.h>
#include <cstdint>

#define NUM_C 8192
#define NUM_B 256
#define NT    512
#define NWARP (NT / 32)
#define EPSF  1e-6f
#define ROW_BYTES (NUM_C * 4)        // 32 KB per row

// cross-block accumulators (allocation-free rule: __device__ globals; reset
// in-kernel after the grid completes so every graph replay starts clean)
__device__ float        g_sum = 0.0f;
__device__ unsigned int g_cnt = 0u;

__device__ __forceinline__ void mbar_wait_parity0(uint32_t mbar_addr) {
    uint32_t done;
    asm volatile(
        "{\n\t.reg .pred p;\n\t"
        "mbarrier.try_wait.parity.acquire.cta.shared::cta.b64 p, [%1], %2;\n\t"
        "selp.b32 %0, 1, 0, p;\n\t}"
        : "=r"(done) : "r"(mbar_addr), "r"(0u) : "memory");
    while (!done) {
        asm volatile(
            "{\n\t.reg .pred p;\n\t"
            "mbarrier.try_wait.parity.acquire.cta.shared::cta.b64 p, [%1], %2, 0x989680;\n\t"
            "selp.b32 %0, 1, 0, p;\n\t}"
            : "=r"(done) : "r"(mbar_addr), "r"(0u) : "memory");
    }
}

__global__ __launch_bounds__(NT, 2)
void seesaw_v7_kernel(const float* __restrict__ logits,
                      const float* __restrict__ targets,
                      const float* __restrict__ s,
                      float* __restrict__ out)
{
    __shared__ alignas(128) float sh_l[NUM_C];       // 32 KB: logits row (bulk-async)
    __shared__ alignas(8)  unsigned long long mbar;
    __shared__ float sh_warp[NWARP];
    __shared__ int   sh_label;

    const int b    = blockIdx.x;
    const int tid  = threadIdx.x;
    const int lane = tid & 31;
    const int wid  = tid >> 5;
    const size_t rowoff = (size_t)b * NUM_C;

    const uint32_t mbar_addr = (uint32_t)__cvta_generic_to_shared(&mbar);
    const uint32_t shl_addr  = (uint32_t)__cvta_generic_to_shared(sh_l);

    // ---- kick off the label-independent logits row copy (zero registers) ----
    if (tid == 0) {
        asm volatile("mbarrier.init.shared.b64 [%0], %1;"
                     :: "r"(mbar_addr), "r"(1) : "memory");
    }
    __syncthreads();
    asm volatile("fence.proxy.async.shared::cta;" ::: "memory");
    if (tid == 0) {
        asm volatile("mbarrier.arrive.expect_tx.shared.b64 _, [%0], %1;"
                     :: "r"(mbar_addr), "r"((uint32_t)ROW_BYTES) : "memory");
        asm volatile(
            "cp.async.bulk.shared::cluster.global.mbarrier::complete_tx::bytes "
            "[%0], [%1], %2, [%3];"
            :: "r"(shl_addr), "l"(logits + rowoff), "r"((uint32_t)ROW_BYTES),
               "r"(mbar_addr) : "memory");
    }

    // ---- targets scan (overlaps the bulk copy): 4 batched int4 loads ----
    {
        const int4* tg4 = (const int4*)(targets + rowoff);
        int4 t0 = tg4[tid + 0 * NT];
        int4 t1 = tg4[tid + 1 * NT];
        int4 t2 = tg4[tid + 2 * NT];
        int4 t3 = tg4[tid + 3 * NT];
        int l = -1;
        if (t0.x | t0.y | t0.z | t0.w) {
            int j = (tid + 0 * NT) * 4;
            l = t0.x ? j : (t0.y ? j + 1 : (t0.z ? j + 2 : j + 3));
        }
        if (t1.x | t1.y | t1.z | t1.w) {
            int j = (tid + 1 * NT) * 4;
            l = t1.x ? j : (t1.y ? j + 1 : (t1.z ? j + 2 : j + 3));
        }
        if (t2.x | t2.y | t2.z | t2.w) {
            int j = (tid + 2 * NT) * 4;
            l = t2.x ? j : (t2.y ? j + 1 : (t2.z ? j + 2 : j + 3));
        }
        if (t3.x | t3.y | t3.z | t3.w) {
            int j = (tid + 3 * NT) * 4;
            l = t3.x ? j : (t3.y ? j + 1 : (t3.z ? j + 2 : j + 3));
        }
        if (l >= 0) sh_label = l;        // exactly one thread writes
    }
    __syncthreads();
    const int lab = sh_label;

    // ---- only label-dependent traffic left: the s row (4 batched float4) ----
    const float4* s4 = (const float4*)(s + (size_t)lab * NUM_C);
    float4 s0 = s4[tid + 0 * NT];
    float4 s1 = s4[tid + 1 * NT];
    float4 s2 = s4[tid + 2 * NT];
    float4 s3 = s4[tid + 3 * NT];

    // logits row has been streaming in since t=0; wait for completion
    mbar_wait_parity0(mbar_addr);

    const float4* lsh4 = (const float4*)sh_l;
    float4 l0 = lsh4[tid + 0 * NT];
    float4 l1 = lsh4[tid + 1 * NT];
    float4 l2 = lsh4[tid + 2 * NT];
    float4 l3 = lsh4[tid + 3 * NT];

    // denom = sum_j s[lab,j]*exp(logits[b,j])  (s diag==1 folds the +expl term;
    // max-shift dropped: it only rescales +eps by e^{-max}, ~1e-8 effect)
    float acc = 0.f;
    acc += s0.x * __expf(l0.x) + s0.y * __expf(l0.y)
         + s0.z * __expf(l0.z) + s0.w * __expf(l0.w);
    acc += s1.x * __expf(l1.x) + s1.y * __expf(l1.y)
         + s1.z * __expf(l1.z) + s1.w * __expf(l1.w);
    acc += s2.x * __expf(l2.x) + s2.y * __expf(l2.y)
         + s2.z * __expf(l2.z) + s2.w * __expf(l2.w);
    acc += s3.x * __expf(l3.x) + s3.y * __expf(l3.y)
         + s3.z * __expf(l3.z) + s3.w * __expf(l3.w);

    // ---- block reduce ----
    #pragma unroll
    for (int off = 16; off > 0; off >>= 1)
        acc += __shfl_down_sync(0xffffffffu, acc, off);
    if (lane == 0) sh_warp[wid] = acc;
    __syncthreads();

    if (wid == 0) {
        float v = (lane < NWARP) ? sh_warp[lane] : 0.f;
        #pragma unroll
        for (int off = 8; off > 0; off >>= 1)
            v += __shfl_down_sync(0xffffffffu, v, off);

        if (lane == 0) {
            float elab  = __expf(sh_l[lab]);        // free: row is in smem
            float sigma = elab / (v + EPSF);
            float loss  = -logf(sigma + EPSF);

            atomicAdd(&g_sum, loss);
            __threadfence();
            unsigned int tkt = atomicAdd(&g_cnt, 1u);
            if (tkt == NUM_B - 1u) {
                float total = atomicExch(&g_sum, 0.0f);   // drain + reset
                g_cnt = 0u;
                out[0] = total * (1.0f / NUM_B);
            }
        }
    }
}

extern "C" void kernel_launch(void* const* d_in, const int* in_sizes, int n_in,
                              void* d_out, int out_size)
{
    const float* logits  = (const float*)d_in[0];
    const float* targets = (const float*)d_in[1];
    const float* s       = (const float*)d_in[2];
    float* out = (float*)d_out;

    seesaw_v7_kernel<<<NUM_B, NT>>>(logits, targets, s, out);
}